// round 6
// baseline (speedup 1.0000x reference)
#include <cuda_runtime.h>

// DynamicMaskHead fused kernel for GB300 (sm_103a), round 6.
// Baseline R5 (64.3us): 400 blocks, one wave at 3 CTA/SM, packed-weight LDS.128.
// R6 changes:
//  - layer-2 weights/bias pre-scaled by 0.5 at repack -> smem holds half-logits;
//    all aligned_bilinear 0.5 factors fold into that or one fmaf.
//  - Phase 2: 8 outputs/thread (LDS.128 + left scalar), odd rows in iterations
//    0-14 and even rows in 15-29 (warp-uniform blend branch, no divergence).
//  - Phase 1: biases folded into first FMA; coordinate term via s + k*d.

#define HH       96
#define WW       160
#define HW       15360
#define OWw      320
#define NP       169
#define NTHREADS 256
#define QW       (WW / 4)

// Repacked weight layout (floats, 16B-aligned base):
//   [0,96)    l0w: 8 ch x 12 (10 weights + 2 pad)
//   [96,104)  l0b: 8
//   [104,168) l1w: 8 ch x 8
//   [168,176) l1b: 8
//   [176,184) l2w: 8   (pre-scaled by 0.5)
//   [184]     l2b      (pre-scaled by 0.5)
#define SW_FLOATS 188
#define SMEM_FLOATS (HW + SW_FLOATS)

// x is already 0.5*logit-combination: sigmoid(L) = 0.5*tanh(0.5L) + 0.5
__device__ __forceinline__ float sig_h(float x) {
    float t;
    asm("tanh.approx.f32 %0, %1;" : "=f"(t) : "f"(x));
    return fmaf(0.5f, t, 0.5f);
}

__global__ __launch_bounds__(NTHREADS, 3)
void dmh_kernel(const float* __restrict__ feats,     // [2, 8, 96, 160]
                const float* __restrict__ p1,        // [N, 169]
                const float* __restrict__ p2,        // [N, 169]
                const float* __restrict__ loc,       // [N, 2]
                const float* __restrict__ off,       // [N, 2]
                const int*   __restrict__ imi,       // [N]
                const int*   __restrict__ fpn,       // [N]
                float*       __restrict__ out)       // [2, N, 192, 320]
{
    extern __shared__ float smem[];
    float* sL = smem;           // [HW] half-logits
    float* sw = smem + HW;      // [SW_FLOATS]

    const int tid    = threadIdx.x;
    const int inst   = blockIdx.x;
    const int head   = blockIdx.y;
    const int n_inst = gridDim.x;

    // ---- Load + repack params (layer-2 pre-scaled by 0.5) ----
    const float* params = (head == 0 ? p1 : p2) + inst * NP;
    if (tid < NP) {
        float w = params[tid];
        int d;
        if      (tid < 80)  { const int c = tid / 10; d = c * 12 + (tid - c * 10); }
        else if (tid < 144) { d = 104 + (tid - 80); }
        else if (tid < 152) { d = 176 + (tid - 144); w *= 0.5f; }
        else if (tid < 160) { d = 96  + (tid - 152); }
        else if (tid < 168) { d = 168 + (tid - 160); }
        else                { d = 184; w *= 0.5f; }
        sw[d] = w;
    }
    if (tid >= 200 && tid < 208) {
        const int c = tid - 200;
        sw[c * 12 + 10] = 0.0f;
        sw[c * 12 + 11] = 0.0f;
    }

    const int   lvl     = fpn[inst];
    const float inv_soi = 1.0f / (64.0f * (float)(1 << lvl));
    float lx = loc[2 * inst + 0];
    float ly = loc[2 * inst + 1];
    if (head) {
        lx += off[2 * inst + 0] * 128.0f;
        ly += off[2 * inst + 1] * 128.0f;
    }
    const float* fb = feats + (size_t)imi[inst] * (8 * HW);
    const float dx = -8.0f * inv_soi;
    __syncthreads();

    // ---------------- Phase 1: MLP, 4 px/thread/iter, 15 iters --------------
    #pragma unroll 1
    for (int q = tid; q < HW / 4; q += NTHREADS) {
        const int row  = q / QW;
        const int px0  = (q - row * QW) * 4;
        const int base = row * WW + px0;

        const float cy  = (ly - (float)(row * 8 + 4)) * inv_soi;
        const float cx0 = (lx - (float)(px0 * 8 + 4)) * inv_soi;

        float4 v[8];
        #pragma unroll
        for (int j = 0; j < 8; ++j)
            v[j] = *reinterpret_cast<const float4*>(fb + j * HW + base);

        // Layer 0: bias + coord folded into linear-in-k start, then features.
        float a[8][4];
        const float4 b0A = *reinterpret_cast<const float4*>(sw + 96);
        const float4 b0B = *reinterpret_cast<const float4*>(sw + 100);
        const float b0v[8] = { b0A.x, b0A.y, b0A.z, b0A.w, b0B.x, b0B.y, b0B.z, b0B.w };
        #pragma unroll
        for (int c = 0; c < 8; ++c) {
            const float4 wA = *reinterpret_cast<const float4*>(sw + c * 12);
            const float4 wB = *reinterpret_cast<const float4*>(sw + c * 12 + 4);
            const float2 wC = *reinterpret_cast<const float2*>(sw + c * 12 + 8);
            const float s = fmaf(wA.x, cx0, fmaf(wA.y, cy, b0v[c]));
            const float d = wA.x * dx;
            float t[4];
            t[0] = s;
            t[1] = s + d;
            t[2] = t[1] + d;
            t[3] = t[2] + d;
            #pragma unroll
            for (int k = 0; k < 4; ++k) {
                float u = t[k];
                u = fmaf(wA.z, (&v[0].x)[k], u);
                u = fmaf(wA.w, (&v[1].x)[k], u);
                u = fmaf(wB.x, (&v[2].x)[k], u);
                u = fmaf(wB.y, (&v[3].x)[k], u);
                u = fmaf(wB.z, (&v[4].x)[k], u);
                u = fmaf(wB.w, (&v[5].x)[k], u);
                u = fmaf(wC.x, (&v[6].x)[k], u);
                u = fmaf(wC.y, (&v[7].x)[k], u);
                a[c][k] = fmaxf(u, 0.0f);
            }
        }

        // Layer 1 (bias folded into first FMA).
        float b[8][4];
        const float4 b1A = *reinterpret_cast<const float4*>(sw + 168);
        const float4 b1B = *reinterpret_cast<const float4*>(sw + 172);
        const float b1v[8] = { b1A.x, b1A.y, b1A.z, b1A.w, b1B.x, b1B.y, b1B.z, b1B.w };
        #pragma unroll
        for (int c = 0; c < 8; ++c) {
            const float4 wA = *reinterpret_cast<const float4*>(sw + 104 + c * 8);
            const float4 wB = *reinterpret_cast<const float4*>(sw + 104 + c * 8 + 4);
            #pragma unroll
            for (int k = 0; k < 4; ++k) {
                float u = fmaf(wA.x, a[0][k], b1v[c]);
                u = fmaf(wA.y, a[1][k], u);
                u = fmaf(wA.z, a[2][k], u);
                u = fmaf(wA.w, a[3][k], u);
                u = fmaf(wB.x, a[4][k], u);
                u = fmaf(wB.y, a[5][k], u);
                u = fmaf(wB.z, a[6][k], u);
                u = fmaf(wB.w, a[7][k], u);
                b[c][k] = fmaxf(u, 0.0f);
            }
        }

        // Layer 2 (weights pre-scaled by 0.5 -> store half-logits).
        {
            const float4 wA = *reinterpret_cast<const float4*>(sw + 176);
            const float4 wB = *reinterpret_cast<const float4*>(sw + 180);
            const float b2 = sw[184];
            float o[4];
            #pragma unroll
            for (int k = 0; k < 4; ++k) {
                float u = fmaf(wA.x, b[0][k], b2);
                u = fmaf(wA.y, b[1][k], u);
                u = fmaf(wA.z, b[2][k], u);
                u = fmaf(wA.w, b[3][k], u);
                u = fmaf(wB.x, b[4][k], u);
                u = fmaf(wB.y, b[5][k], u);
                u = fmaf(wB.z, b[6][k], u);
                u = fmaf(wB.w, b[7][k], u);
                o[k] = u;
            }
            *reinterpret_cast<float4*>(sL + base) = make_float4(o[0], o[1], o[2], o[3]);
        }
    }
    __syncthreads();

    // ---------------- Phase 2: aligned_bilinear x2 + sigmoid -----------------
    // 8 outputs per thread. sL holds P = 0.5*logit.
    // odd output rows (it 0..14):   n_i = P[r][*]           (r = oy>>1)
    // even output rows (it 15..29): n_i = 0.5*(P[r-1]+P[r]) (r0 clamped at oy=0)
    // odd cols:  sig_h(n_c);  even cols: sig_h(0.5*(n_{c-1}+n_c))
    float* ob = out + ((size_t)head * n_inst + inst) * (size_t)(2 * HH * OWw);

    #pragma unroll 1
    for (int it = 0; it < 30; ++it) {
        const int u  = tid + it * NTHREADS;          // [0, 7680)
        const bool odd_half = (u < 3840);
        const int v  = odd_half ? u : (u - 3840);
        const int q  = v / 40;                        // row index 0..95
        const int jg = v - q * 40;                    // col group 0..39
        const int oy = odd_half ? (2 * q + 1) : (2 * q);
        const int c0 = jg * 4;

        const int r1 = q;
        const float* rowA = sL + r1 * WW + c0;

        float nm, n0, n1, n2, n3;
        if (odd_half) {
            const float4 qa = *reinterpret_cast<const float4*>(rowA);
            const float  la = (jg > 0) ? rowA[-1] : qa.x;
            nm = la; n0 = qa.x; n1 = qa.y; n2 = qa.z; n3 = qa.w;
        } else {
            const int r0 = (r1 == 0) ? 0 : r1 - 1;
            const float* rowB = sL + r0 * WW + c0;
            const float4 qa = *reinterpret_cast<const float4*>(rowA);
            const float4 qb = *reinterpret_cast<const float4*>(rowB);
            const float  la = (jg > 0) ? rowA[-1] : qa.x;
            const float  lb = (jg > 0) ? rowB[-1] : qb.x;
            nm = 0.5f * (la + lb);
            n0 = 0.5f * (qa.x + qb.x);
            n1 = 0.5f * (qa.y + qb.y);
            n2 = 0.5f * (qa.z + qb.z);
            n3 = 0.5f * (qa.w + qb.w);
        }

        float4 o1, o2;
        o1.x = sig_h(fmaf(0.5f, nm, 0.5f * n0));
        o1.y = sig_h(n0);
        o1.z = sig_h(fmaf(0.5f, n0, 0.5f * n1));
        o1.w = sig_h(n1);
        o2.x = sig_h(fmaf(0.5f, n1, 0.5f * n2));
        o2.y = sig_h(n2);
        o2.z = sig_h(fmaf(0.5f, n2, 0.5f * n3));
        o2.w = sig_h(n3);

        float* op = ob + oy * OWw + jg * 8;
        *reinterpret_cast<float4*>(op)     = o1;
        *reinterpret_cast<float4*>(op + 4) = o2;
    }
}

extern "C" void kernel_launch(void* const* d_in, const int* in_sizes, int n_in,
                              void* d_out, int out_size)
{
    const float* feats = (const float*)d_in[0];
    const float* p1    = (const float*)d_in[1];
    const float* p2    = (const float*)d_in[2];
    const float* loc   = (const float*)d_in[3];
    const float* off   = (const float*)d_in[4];
    const int*   imi   = (const int*)  d_in[5];
    const int*   fpn   = (const int*)  d_in[6];
    float* out = (float*)d_out;

    const int n_inst = in_sizes[5];   // 200
    const size_t smem_bytes = (size_t)SMEM_FLOATS * sizeof(float);  // ~62.2 KB

    static bool attr_set = false;
    if (!attr_set) {
        cudaFuncSetAttribute(dmh_kernel,
                             cudaFuncAttributeMaxDynamicSharedMemorySize,
                             (int)smem_bytes);
        attr_set = true;
    }

    dim3 grid(n_inst, 2);             // 400 blocks -> one wave at 3 CTA/SM
    dmh_kernel<<<grid, NTHREADS, smem_bytes>>>(feats, p1, p2, loc, off, imi, fpn, out);
}